// round 3
// baseline (speedup 1.0000x reference)
#include <cuda_runtime.h>
#include <cstdint>
#include <cstddef>

// ---------------------------------------------------------------------------
// TextLSTM: only batch column 63 of the (S=1024, T=64) token matrix reaches the
// output (h[:, T-1, :]), and LSTM batch elements are independent.  So we run a
// batch-1, 1024-step, 3-layer LSTM:
//   1) gemm0: XG0[t] = Wih0 @ emb[tokens[t,63]] + bih0 + bhh0   (time-parallel)
//   2) persistent pipelined kernel: per tick k, layer0 computes step k,
//      layer1 step k-1, layer2 step k-2.  Weights live in SMEM (one slice per
//      CTA), h vectors go through L2, one global spin barrier per tick.
//   3) head: out[t] = h2[t] @ Wlin^T + blin
// ---------------------------------------------------------------------------

#define S_LEN   1024
#define E_DIM   512
#define H0_DIM  1024
#define H1_DIM  512
#define H2_DIM  256
#define OUT_DIM 7

#define NCTA0 74          // layer0 CTAs: up to 14 units * 16KB = 224KB SMEM
#define NCTA1 57          // layer1 CTAs: up to  9 units * 24KB = 216KB
#define NCTA2 15          // layer2 CTAs: up to 18 units * 12KB = 216KB
#define NCTA  (NCTA0 + NCTA1 + NCTA2)   // 146 <= 148 SMs -> all co-resident
#define TICKS (S_LEN + 2)

// max dynamic SMEM (floats): layer0 worst case U=14:
//   weights 56*1024 + partial 56*8 + c 14 + bias 56 = 57862 floats = 231448 B
#define LSTM_SMEM_BYTES 231448

// -------------------- scratch (device globals; no runtime alloc) -----------
__device__ float    d_XG0[(size_t)S_LEN * 4 * H0_DIM];      // 16 MB
__device__ float    d_H0[(size_t)(S_LEN + 1) * H0_DIM];     // slot s = h0[s-1]
__device__ float    d_H1[(size_t)(S_LEN + 1) * H1_DIM];
__device__ float    d_H2[(size_t)(S_LEN + 1) * H2_DIM];
__device__ unsigned d_bar;

// -------------------- init: zero h(-1) slots + barrier ---------------------
__global__ void init_kernel() {
    int tid = threadIdx.x;
    if (tid < H0_DIM) d_H0[tid] = 0.f;
    if (tid < H1_DIM) d_H1[tid] = 0.f;
    if (tid < H2_DIM) d_H2[tid] = 0.f;
    if (tid == 0) d_bar = 0u;
}

// -------------------- gemm0: XG0 = gather(emb) @ Wih0^T + biases -----------
// C[t][g], tiles 64x64, BK=16, 256 threads, 4x4 microtile.
__global__ __launch_bounds__(256) void gemm0_kernel(
    const int* __restrict__ tokens, const float* __restrict__ emb,
    const float* __restrict__ Wih0, const float* __restrict__ bih0,
    const float* __restrict__ bhh0)
{
    __shared__ float As[16][64];
    __shared__ float Bs[16][64];
    const int g0  = blockIdx.x * 64;
    const int t0  = blockIdx.y * 64;
    const int tid = threadIdx.x;
    const int tx  = tid & 15, ty = tid >> 4;
    const int ltt = tid & 63;           // row within tile for loads
    const int lk4 = (tid >> 6) << 2;    // k offset {0,4,8,12}

    const int tokA = tokens[(t0 + ltt) * 64 + 63];

    float acc[4][4];
#pragma unroll
    for (int i = 0; i < 4; i++)
#pragma unroll
        for (int j = 0; j < 4; j++) acc[i][j] = 0.f;

    for (int k0 = 0; k0 < E_DIM; k0 += 16) {
        float4 av = *(const float4*)&emb[(size_t)tokA * E_DIM + k0 + lk4];
        float4 bv = *(const float4*)&Wih0[(size_t)(g0 + ltt) * E_DIM + k0 + lk4];
        As[lk4 + 0][ltt] = av.x; As[lk4 + 1][ltt] = av.y;
        As[lk4 + 2][ltt] = av.z; As[lk4 + 3][ltt] = av.w;
        Bs[lk4 + 0][ltt] = bv.x; Bs[lk4 + 1][ltt] = bv.y;
        Bs[lk4 + 2][ltt] = bv.z; Bs[lk4 + 3][ltt] = bv.w;
        __syncthreads();
#pragma unroll
        for (int kk = 0; kk < 16; kk++) {
            float4 a4 = *(const float4*)&As[kk][ty * 4];
            float4 b4 = *(const float4*)&Bs[kk][tx * 4];
            float a[4] = {a4.x, a4.y, a4.z, a4.w};
            float bb[4] = {b4.x, b4.y, b4.z, b4.w};
#pragma unroll
            for (int i = 0; i < 4; i++)
#pragma unroll
                for (int j = 0; j < 4; j++) acc[i][j] += a[i] * bb[j];
        }
        __syncthreads();
    }
#pragma unroll
    for (int i = 0; i < 4; i++) {
        const int t = t0 + ty * 4 + i;
#pragma unroll
        for (int j = 0; j < 4; j++) {
            const int g = g0 + tx * 4 + j;
            d_XG0[(size_t)t * (4 * H0_DIM) + g] = acc[i][j] + bih0[g] + bhh0[g];
        }
    }
}

// -------------------- persistent pipelined LSTM ----------------------------
__device__ __forceinline__ float sigm_(float x) { return 1.f / (1.f + expf(-x)); }

__global__ void __launch_bounds__(1024, 1) lstm_kernel(
    const float* __restrict__ Whh0,
    const float* __restrict__ Wih1, const float* __restrict__ Whh1,
    const float* __restrict__ bih1, const float* __restrict__ bhh1,
    const float* __restrict__ Wih2, const float* __restrict__ Whh2,
    const float* __restrict__ bih2, const float* __restrict__ bhh2)
{
    extern __shared__ float sm[];
    const int b   = blockIdx.x;
    const int tid = threadIdx.x;

    int layer, ubase, U, W, CG, Hout;
    if (b < NCTA0) {
        layer = 0; int i = b;
        ubase = i * H0_DIM / NCTA0; U = (i + 1) * H0_DIM / NCTA0 - ubase;
        W = H0_DIM; CG = 8; Hout = H0_DIM;            // x = h0[t-1]
    } else if (b < NCTA0 + NCTA1) {
        layer = 1; int i = b - NCTA0;
        ubase = i * H1_DIM / NCTA1; U = (i + 1) * H1_DIM / NCTA1 - ubase;
        W = H0_DIM + H1_DIM; CG = 12; Hout = H1_DIM;  // x = [h0[t] | h1[t-1]]
    } else {
        layer = 2; int i = b - NCTA0 - NCTA1;
        ubase = i * H2_DIM / NCTA2; U = (i + 1) * H2_DIM / NCTA2 - ubase;
        W = H1_DIM + H2_DIM; CG = 6; Hout = H2_DIM;   // x = [h1[t] | h2[t-1]]
    }
    const int RG   = 32 / CG;
    const int rows = 4 * U;                 // local row lr = 4*u + gate

    float* wsm     = sm;                    // [rows][W]
    float* partial = wsm + rows * W;        // [rows][CG]
    float* csm     = partial + rows * CG;   // [U]
    float* bsm     = csm + U;               // [rows]

    // ---- load weight slice into SMEM (row-major, float4) ----
    const int wq  = W >> 2;
    const int nf4 = rows * wq;
    for (int i = tid; i < nf4; i += 1024) {
        const int lr = i / wq;
        const int c  = (i - lr * wq) << 2;
        const int u = lr >> 2, gate = lr & 3;
        const int grow = gate * Hout + ubase + u;
        float4 v;
        if (layer == 0) {
            v = *(const float4*)&Whh0[(size_t)grow * H0_DIM + c];
        } else if (layer == 1) {
            v = (c < H0_DIM) ? *(const float4*)&Wih1[(size_t)grow * H0_DIM + c]
                             : *(const float4*)&Whh1[(size_t)grow * H1_DIM + (c - H0_DIM)];
        } else {
            v = (c < H1_DIM) ? *(const float4*)&Wih2[(size_t)grow * H1_DIM + c]
                             : *(const float4*)&Whh2[(size_t)grow * H2_DIM + (c - H1_DIM)];
        }
        *(float4*)&wsm[lr * W + c] = v;
    }
    for (int i = tid; i < rows; i += 1024) {
        const int u = i >> 2, gate = i & 3;
        const int grow = gate * Hout + ubase + u;
        bsm[i] = (layer == 1) ? (bih1[grow] + bhh1[grow])
               : (layer == 2) ? (bih2[grow] + bhh2[grow]) : 0.f;
    }
    for (int i = tid; i < U; i += 1024) csm[i] = 0.f;
    __syncthreads();

    const int wid  = tid >> 5, lane = tid & 31;
    const int cg   = wid % CG, rg = wid / CG;
    const bool mv  = (wid < CG * RG);       // matvec-active warp
    const int col  = cg * 128 + lane * 4;   // this lane's 4 input columns

    for (int tick = 0; tick < TICKS; ++tick) {
        const int t = tick - layer;
        const bool active = (t >= 0) && (t < S_LEN);

        float xg0r[4];
        if (active) {
            if (layer == 0 && tid < U) {    // prefetch precomputed input gates
#pragma unroll
                for (int g = 0; g < 4; g++)
                    xg0r[g] = d_XG0[(size_t)t * (4 * H0_DIM) + g * H0_DIM + ubase + tid];
            }
            if (mv) {
                const float* xp;
                if (layer == 0)
                    xp = d_H0 + (size_t)t * H0_DIM + col;                 // h0[t-1]
                else if (layer == 1)
                    xp = (col < H0_DIM)
                       ? d_H0 + (size_t)(t + 1) * H0_DIM + col            // h0[t]
                       : d_H1 + (size_t)t * H1_DIM + (col - H0_DIM);      // h1[t-1]
                else
                    xp = (col < H1_DIM)
                       ? d_H1 + (size_t)(t + 1) * H1_DIM + col            // h1[t]
                       : d_H2 + (size_t)t * H2_DIM + (col - H1_DIM);      // h2[t-1]
                const float4 x4 = __ldcg((const float4*)xp);

                for (int lr = rg; lr < rows; lr += RG) {
                    const float4 w = *(const float4*)&wsm[lr * W + col];
                    float s = w.x * x4.x + w.y * x4.y + w.z * x4.z + w.w * x4.w;
                    s += __shfl_xor_sync(0xffffffffu, s, 16);
                    s += __shfl_xor_sync(0xffffffffu, s, 8);
                    s += __shfl_xor_sync(0xffffffffu, s, 4);
                    s += __shfl_xor_sync(0xffffffffu, s, 2);
                    s += __shfl_xor_sync(0xffffffffu, s, 1);
                    if (lane == 0) partial[lr * CG + cg] = s;
                }
            }
        }
        __syncthreads();

        if (active && tid < U) {
            float acc[4];
#pragma unroll
            for (int g = 0; g < 4; g++) {
                float a = (layer == 0) ? xg0r[g] : bsm[tid * 4 + g];
                for (int j = 0; j < CG; j++) a += partial[(tid * 4 + g) * CG + j];
                acc[g] = a;
            }
            const float ig = sigm_(acc[0]);
            const float fg = sigm_(acc[1]);
            const float gg = tanhf(acc[2]);
            const float og = sigm_(acc[3]);
            const float c  = fg * csm[tid] + ig * gg;
            csm[tid] = c;
            const float h  = og * tanhf(c);
            if (layer == 0)      __stcg(&d_H0[(size_t)(t + 1) * H0_DIM + ubase + tid], h);
            else if (layer == 1) __stcg(&d_H1[(size_t)(t + 1) * H1_DIM + ubase + tid], h);
            else                 __stcg(&d_H2[(size_t)(t + 1) * H2_DIM + ubase + tid], h);
            __threadfence();     // writer-side release of h before barrier
        }
        __syncthreads();

        // ---- grid-wide spin barrier (all 146 CTAs co-resident) ----
        if (tid == 0) {
            __threadfence();
            atomicAdd(&d_bar, 1u);
            const unsigned target = (unsigned)(tick + 1) * (unsigned)NCTA;
            while (*(volatile unsigned*)&d_bar < target) { __nanosleep(64); }
            __threadfence();     // acquire before next tick's loads
        }
        __syncthreads();
    }
}

// -------------------- head: out = H2 @ Wlin^T + blin -----------------------
__global__ __launch_bounds__(256) void head_kernel(
    const float* __restrict__ Wlin, const float* __restrict__ blin,
    float* __restrict__ out)
{
    const int t = blockIdx.x;
    const int w = threadIdx.x >> 5, lane = threadIdx.x & 31;
    if (w >= OUT_DIM) return;
    const float* h  = d_H2 + (size_t)(t + 1) * H2_DIM;
    const float* wl = Wlin + (size_t)w * H2_DIM;
    float s = 0.f;
#pragma unroll
    for (int j = 0; j < H2_DIM / 32; j++) s += h[lane + 32 * j] * wl[lane + 32 * j];
    s += __shfl_xor_sync(0xffffffffu, s, 16);
    s += __shfl_xor_sync(0xffffffffu, s, 8);
    s += __shfl_xor_sync(0xffffffffu, s, 4);
    s += __shfl_xor_sync(0xffffffffu, s, 2);
    s += __shfl_xor_sync(0xffffffffu, s, 1);
    if (lane == 0) out[t * OUT_DIM + w] = s + blin[w];
}

// ---------------------------------------------------------------------------
extern "C" void kernel_launch(void* const* d_in, const int* in_sizes, int n_in,
                              void* d_out, int out_size)
{
    const int*   tokens = (const int*)  d_in[0];
    const float* emb    = (const float*)d_in[1];
    const float* Wih0   = (const float*)d_in[2];
    const float* Whh0   = (const float*)d_in[3];
    const float* bih0   = (const float*)d_in[4];
    const float* bhh0   = (const float*)d_in[5];
    const float* Wih1   = (const float*)d_in[6];
    const float* Whh1   = (const float*)d_in[7];
    const float* bih1   = (const float*)d_in[8];
    const float* bhh1   = (const float*)d_in[9];
    const float* Wih2   = (const float*)d_in[10];
    const float* Whh2   = (const float*)d_in[11];
    const float* bih2   = (const float*)d_in[12];
    const float* bhh2   = (const float*)d_in[13];
    const float* Wlin   = (const float*)d_in[14];
    const float* blin   = (const float*)d_in[15];
    float* out = (float*)d_out;

    cudaFuncSetAttribute(lstm_kernel, cudaFuncAttributeMaxDynamicSharedMemorySize,
                         LSTM_SMEM_BYTES);

    init_kernel<<<1, 1024>>>();
    gemm0_kernel<<<dim3(4 * H0_DIM / 64, S_LEN / 64), 256>>>(tokens, emb, Wih0, bih0, bhh0);
    lstm_kernel<<<NCTA, 1024, LSTM_SMEM_BYTES>>>(Whh0, Wih1, Whh1, bih1, bhh1,
                                                 Wih2, Whh2, bih2, bhh2);
    head_kernel<<<S_LEN, 256>>>(Wlin, blin, out);
}

// round 4
// speedup vs baseline: 1.2603x; 1.2603x over previous
#include <cuda_runtime.h>
#include <cstdint>
#include <cstddef>

// ---------------------------------------------------------------------------
// TextLSTM: only batch column 63 reaches the output -> batch-1, 1024-step,
// 3-layer LSTM.
//  1) gemm0: XG0[t] = Wih0 @ emb[tok[t,63]] + bih0 + bhh0       (parallel in t)
//  2) lstm:  persistent kernel, 146 CTAs (74/57/15 per layer), weights in SMEM.
//     Shuffle-free matvec: thread (r,g) serially accumulates its column group,
//     broadcast x from SMEM.  Per-layer progress counters replace the global
//     barrier: layer L at step t spins on cnt[L-1] >= N*(t+1), cnt[L] >= N*t.
//  3) head:  out[t] = h2[t] @ Wlin^T + blin
// ---------------------------------------------------------------------------

#define S_LEN   1024
#define E_DIM   512
#define H0_DIM  1024
#define H1_DIM  512
#define H2_DIM  256
#define OUT_DIM 7

#define NCTA0 74
#define NCTA1 57
#define NCTA2 15
#define NCTA  (NCTA0 + NCTA1 + NCTA2)   // 146 <= 148 SMs, 1 CTA/SM, co-resident

#define BLOCK 896

// worst-case dynamic SMEM: layer0 U=14: w 229376 + xbuf 2048 + csm 56 = 231480
#define LSTM_SMEM_BYTES 231480

// -------------------- scratch (device globals) -----------------------------
__device__ float    d_XG0[(size_t)S_LEN * 4 * H0_DIM];
__device__ float    d_H0[(size_t)(S_LEN + 1) * H0_DIM];   // slot s = h0[s-1]
__device__ float    d_H1[(size_t)(S_LEN + 1) * H1_DIM];
__device__ float    d_H2[(size_t)(S_LEN + 1) * H2_DIM];
__device__ unsigned d_cnt[3];

__global__ void init_kernel() {
    int tid = threadIdx.x;
    if (tid < H0_DIM) d_H0[tid] = 0.f;
    if (tid < H1_DIM) d_H1[tid] = 0.f;
    if (tid < H2_DIM) d_H2[tid] = 0.f;
    if (tid < 3)      d_cnt[tid] = 0u;
}

// -------------------- gemm0 (unchanged, validated) -------------------------
__global__ __launch_bounds__(256) void gemm0_kernel(
    const int* __restrict__ tokens, const float* __restrict__ emb,
    const float* __restrict__ Wih0, const float* __restrict__ bih0,
    const float* __restrict__ bhh0)
{
    __shared__ float As[16][64];
    __shared__ float Bs[16][64];
    const int g0  = blockIdx.x * 64;
    const int t0  = blockIdx.y * 64;
    const int tid = threadIdx.x;
    const int tx  = tid & 15, ty = tid >> 4;
    const int ltt = tid & 63;
    const int lk4 = (tid >> 6) << 2;

    const int tokA = tokens[(t0 + ltt) * 64 + 63];

    float acc[4][4];
#pragma unroll
    for (int i = 0; i < 4; i++)
#pragma unroll
        for (int j = 0; j < 4; j++) acc[i][j] = 0.f;

    for (int k0 = 0; k0 < E_DIM; k0 += 16) {
        float4 av = *(const float4*)&emb[(size_t)tokA * E_DIM + k0 + lk4];
        float4 bv = *(const float4*)&Wih0[(size_t)(g0 + ltt) * E_DIM + k0 + lk4];
        As[lk4 + 0][ltt] = av.x; As[lk4 + 1][ltt] = av.y;
        As[lk4 + 2][ltt] = av.z; As[lk4 + 3][ltt] = av.w;
        Bs[lk4 + 0][ltt] = bv.x; Bs[lk4 + 1][ltt] = bv.y;
        Bs[lk4 + 2][ltt] = bv.z; Bs[lk4 + 3][ltt] = bv.w;
        __syncthreads();
#pragma unroll
        for (int kk = 0; kk < 16; kk++) {
            float4 a4 = *(const float4*)&As[kk][ty * 4];
            float4 b4 = *(const float4*)&Bs[kk][tx * 4];
            float a[4] = {a4.x, a4.y, a4.z, a4.w};
            float bb[4] = {b4.x, b4.y, b4.z, b4.w};
#pragma unroll
            for (int i = 0; i < 4; i++)
#pragma unroll
                for (int j = 0; j < 4; j++) acc[i][j] += a[i] * bb[j];
        }
        __syncthreads();
    }
#pragma unroll
    for (int i = 0; i < 4; i++) {
        const int t = t0 + ty * 4 + i;
#pragma unroll
        for (int j = 0; j < 4; j++) {
            const int g = g0 + tx * 4 + j;
            d_XG0[(size_t)t * (4 * H0_DIM) + g] = acc[i][j] + bih0[g] + bhh0[g];
        }
    }
}

// -------------------- persistent LSTM --------------------------------------
__device__ __forceinline__ float sigm_(float x) { return 1.f / (1.f + expf(-x)); }

__device__ __forceinline__ void spin_ge(volatile unsigned* p, unsigned target) {
    while (*p < target) { __nanosleep(32); }
}

// LAYER-templated worker.  Layout per CTA:
//   w4_sm [C4][rows]  (float4, row r = u + U*gate, conflict-free for mv)
//   xbuf  [XCHUNK] float4   (aliased by partial[NG][rows] after mv, except L2)
//   (L2: separate partial)   bias[rows] (L1/L2)   csm[U]
template <int LAYER>
__device__ void run_layer(
    int ci,
    const float* __restrict__ Wa, const float* __restrict__ Wb,
    const float* __restrict__ bih, const float* __restrict__ bhh)
{
    // ---- compile-time config ----
    constexpr int HOUT   = (LAYER == 0) ? H0_DIM : (LAYER == 1) ? H1_DIM : H2_DIM;
    constexpr int WTOT   = (LAYER == 0) ? H0_DIM : (LAYER == 1) ? (H0_DIM + H1_DIM)
                                                                : (H1_DIM + H2_DIM);
    constexpr int WA     = (LAYER == 0) ? H0_DIM : (LAYER == 1) ? H0_DIM : H1_DIM;
    constexpr int C4     = WTOT / 4;
    constexpr int NG     = (LAYER == 0) ? 8 : (LAYER == 1) ? 16 : 12;
    constexpr int PASSES = (LAYER == 0) ? 2 : 1;
    constexpr int XCHUNK = C4 / PASSES;           // float4s staged per pass
    constexpr int GC4P   = XCHUNK / NG;           // c4 iters per thread per pass
    constexpr int NL     = (LAYER == 0) ? NCTA0 : (LAYER == 1) ? NCTA1 : NCTA2;

    const int tid   = threadIdx.x;
    const int ubase = ci * HOUT / NL;
    const int U     = (ci + 1) * HOUT / NL - ubase;
    const int rows  = 4 * U;

    extern __shared__ float sm[];
    float4* w4   = (float4*)sm;                       // C4*rows float4
    float4* xbuf = w4 + C4 * rows;                    // XCHUNK float4
    float*  partial = (LAYER == 2) ? (float*)(xbuf + XCHUNK) : (float*)xbuf;
    float*  bsm  = (LAYER == 2) ? partial + NG * rows : (float*)(xbuf + XCHUNK);
    float*  csm  = (LAYER == 0) ? bsm : bsm + rows;   // L0 has no bias array

    // ---- one-time: load weight slice (coalesced LDG, strided STS) ----
    for (int i = tid; i < C4 * rows; i += BLOCK) {
        const int c4 = i % C4;
        const int r  = i / C4;
        const int u  = r % U, gate = r / U;
        const int grow = gate * HOUT + ubase + u;
        const int col  = c4 * 4;
        float4 v;
        if (LAYER == 0) {
            v = *(const float4*)&Wa[(size_t)grow * WA + col];
        } else {
            v = (col < WA) ? *(const float4*)&Wa[(size_t)grow * WA + col]
                           : *(const float4*)&Wb[(size_t)grow * HOUT + (col - WA)];
        }
        w4[c4 * rows + r] = v;
    }
    if (LAYER != 0) {
        for (int r = tid; r < rows; r += BLOCK) {
            const int u = r % U, gate = r / U;
            const int grow = gate * HOUT + ubase + u;
            bsm[r] = bih[grow] + bhh[grow];
        }
    }
    for (int i = tid; i < U; i += BLOCK) csm[i] = 0.f;
    __syncthreads();

    // ---- per-thread roles ----
    const bool mv = (tid < NG * rows);
    const int  g  = mv ? tid / rows : 0;
    const int  r  = mv ? tid - g * rows : 0;

    for (int t = 0; t < S_LEN; ++t) {
        // L0 combine base: precomputed input gates (independent of deps -> early)
        float xg0r[4];
        if (LAYER == 0 && tid < U) {
#pragma unroll
            for (int gg = 0; gg < 4; gg++)
                xg0r[gg] = __ldg(&d_XG0[(size_t)t * (4 * H0_DIM) + gg * H0_DIM + ubase + tid]);
        }

        // ---- dependency spin (acquire) ----
        if (tid == 0) {
            if (LAYER == 1) spin_ge(&d_cnt[0], (unsigned)(NCTA0 * (t + 1)));
            if (LAYER == 2) spin_ge(&d_cnt[1], (unsigned)(NCTA1 * (t + 1)));
            if (t > 0) {
                if (LAYER == 0) spin_ge(&d_cnt[0], (unsigned)(NCTA0 * t));
                if (LAYER == 1) spin_ge(&d_cnt[1], (unsigned)(NCTA1 * t));
                if (LAYER == 2) spin_ge(&d_cnt[2], (unsigned)(NCTA2 * t));
            }
            __threadfence();
        }
        __syncthreads();

        // ---- stage x (+ register prefetch of pass 2 for L0) ----
        float4 x2r;
        if (tid < XCHUNK) {
            const float4* xsrcA;
            const float4* xsrcB = nullptr;
            if (LAYER == 0) {
                xsrcA = (const float4*)(d_H0 + (size_t)t * H0_DIM);           // h0[t-1]
            } else if (LAYER == 1) {
                xsrcA = (const float4*)(d_H0 + (size_t)(t + 1) * H0_DIM);     // h0[t]
                xsrcB = (const float4*)(d_H1 + (size_t)t * H1_DIM);           // h1[t-1]
            } else {
                xsrcA = (const float4*)(d_H1 + (size_t)(t + 1) * H1_DIM);     // h1[t]
                xsrcB = (const float4*)(d_H2 + (size_t)t * H2_DIM);           // h2[t-1]
            }
            constexpr int A4 = WA / 4;
            if (LAYER == 0) {
                xbuf[tid] = __ldcg(xsrcA + tid);
                x2r       = __ldcg(xsrcA + XCHUNK + tid);
            } else {
                xbuf[tid] = (tid < A4) ? __ldcg(xsrcA + tid) : __ldcg(xsrcB + (tid - A4));
            }
        }
        __syncthreads();

        // ---- matvec ----
        float acc = 0.f;
#pragma unroll
        for (int p = 0; p < PASSES; ++p) {
            if (p > 0) {                      // L0 pass 2: swap in prefetched x
                __syncthreads();              // mv pass-1 reads done
                if (tid < XCHUNK) xbuf[tid] = x2r;
                __syncthreads();
            }
            if (mv) {
                const float4* wp = w4 + (size_t)(p * XCHUNK + g * GC4P) * rows + r;
                const float4* xp = xbuf + g * GC4P;
#pragma unroll
                for (int i = 0; i < GC4P; ++i) {
                    const float4 w = wp[(size_t)i * rows];
                    const float4 x = xp[i];
                    acc += w.x * x.x + w.y * x.y + w.z * x.z + w.w * x.w;
                }
            }
        }
        __syncthreads();                      // x reads done -> partial may alias
        if (mv) partial[g * rows + r] = acc;  // conflict-free STS
        __syncthreads();

        // ---- combine: gate sums, activations, h/c update, release ----
        if (tid < U) {
            float pre[4];
#pragma unroll
            for (int gg = 0; gg < 4; gg++) {
                const int rr = tid + U * gg;
                float a = (LAYER == 0) ? xg0r[gg] : bsm[rr];
#pragma unroll 4
                for (int j = 0; j < NG; j++) a += partial[j * rows + rr];
                pre[gg] = a;
            }
            const float ig = sigm_(pre[0]);
            const float fg = sigm_(pre[1]);
            const float gg_ = tanhf(pre[2]);
            const float og = sigm_(pre[3]);
            const float c  = fg * csm[tid] + ig * gg_;
            csm[tid] = c;
            const float h = og * tanhf(c);
            if (LAYER == 0)      __stcg(&d_H0[(size_t)(t + 1) * H0_DIM + ubase + tid], h);
            else if (LAYER == 1) __stcg(&d_H1[(size_t)(t + 1) * H1_DIM + ubase + tid], h);
            else                 __stcg(&d_H2[(size_t)(t + 1) * H2_DIM + ubase + tid], h);
            __threadfence();                  // release h
        }
        __syncwarp();
        if (tid == 0) atomicAdd(&d_cnt[LAYER], 1u);
        // next tick's spin+syncthreads orders everything else
    }
}

__global__ void __launch_bounds__(BLOCK, 1) lstm_kernel(
    const float* __restrict__ Whh0,
    const float* __restrict__ Wih1, const float* __restrict__ Whh1,
    const float* __restrict__ bih1, const float* __restrict__ bhh1,
    const float* __restrict__ Wih2, const float* __restrict__ Whh2,
    const float* __restrict__ bih2, const float* __restrict__ bhh2)
{
    const int b = blockIdx.x;
    if (b < NCTA0) {
        run_layer<0>(b, Whh0, nullptr, nullptr, nullptr);
    } else if (b < NCTA0 + NCTA1) {
        run_layer<1>(b - NCTA0, Wih1, Whh1, bih1, bhh1);
    } else {
        run_layer<2>(b - NCTA0 - NCTA1, Wih2, Whh2, bih2, bhh2);
    }
}

// -------------------- head -------------------------------------------------
__global__ __launch_bounds__(256) void head_kernel(
    const float* __restrict__ Wlin, const float* __restrict__ blin,
    float* __restrict__ out)
{
    const int t = blockIdx.x;
    const int w = threadIdx.x >> 5, lane = threadIdx.x & 31;
    if (w >= OUT_DIM) return;
    const float* h  = d_H2 + (size_t)(t + 1) * H2_DIM;
    const float* wl = Wlin + (size_t)w * H2_DIM;
    float s = 0.f;
#pragma unroll
    for (int j = 0; j < H2_DIM / 32; j++) s += h[lane + 32 * j] * wl[lane + 32 * j];
    s += __shfl_xor_sync(0xffffffffu, s, 16);
    s += __shfl_xor_sync(0xffffffffu, s, 8);
    s += __shfl_xor_sync(0xffffffffu, s, 4);
    s += __shfl_xor_sync(0xffffffffu, s, 2);
    s += __shfl_xor_sync(0xffffffffu, s, 1);
    if (lane == 0) out[t * OUT_DIM + w] = s + blin[w];
}

// ---------------------------------------------------------------------------
extern "C" void kernel_launch(void* const* d_in, const int* in_sizes, int n_in,
                              void* d_out, int out_size)
{
    const int*   tokens = (const int*)  d_in[0];
    const float* emb    = (const float*)d_in[1];
    const float* Wih0   = (const float*)d_in[2];
    const float* Whh0   = (const float*)d_in[3];
    const float* bih0   = (const float*)d_in[4];
    const float* bhh0   = (const float*)d_in[5];
    const float* Wih1   = (const float*)d_in[6];
    const float* Whh1   = (const float*)d_in[7];
    const float* bih1   = (const float*)d_in[8];
    const float* bhh1   = (const float*)d_in[9];
    const float* Wih2   = (const float*)d_in[10];
    const float* Whh2   = (const float*)d_in[11];
    const float* bih2   = (const float*)d_in[12];
    const float* bhh2   = (const float*)d_in[13];
    const float* Wlin   = (const float*)d_in[14];
    const float* blin   = (const float*)d_in[15];
    float* out = (float*)d_out;

    cudaFuncSetAttribute(lstm_kernel, cudaFuncAttributeMaxDynamicSharedMemorySize,
                         LSTM_SMEM_BYTES);

    init_kernel<<<1, 1024>>>();
    gemm0_kernel<<<dim3(4 * H0_DIM / 64, S_LEN / 64), 256>>>(tokens, emb, Wih0, bih0, bhh0);
    lstm_kernel<<<NCTA, BLOCK, LSTM_SMEM_BYTES>>>(Whh0, Wih1, Whh1, bih1, bhh1,
                                                  Wih2, Whh2, bih2, bhh2);
    head_kernel<<<S_LEN, 256>>>(Wlin, blin, out);
}